// round 2
// baseline (speedup 1.0000x reference)
#include <cuda_runtime.h>
#include <math.h>

// Problem constants (fixed by setup_inputs)
#define N_  4
#define A_  3
#define S_  13
#define NC  80
#define NM  32
#define G_  16
#define H_  104
#define W_  104
#define PC  (5 + NC + NM)   // 117
#define HW  (H_ * W_)       // 10816
#define NCELL (N_ * A_ * S_ * S_)  // 2028
#define NQ  10               // partial fields per cell

// SoA partials: [field][cell]. Every slot overwritten each replay -> no zeroing.
__device__ float        g_part[NQ][NCELL];
__device__ unsigned int g_count = 0;   // zero at load; last block resets to 0

__device__ __forceinline__ float bce_logits(float x, float z) {
    return fmaxf(x, 0.0f) - x * z + log1pf(expf(-fabsf(x)));
}

// field indices
// 0: noobj_bce  1: n_noobj  2: obj_bce  3: (1-giou)  4: xy_bce
// 5: wh_mse     6: cls_nll  7: seg_mean 8: n_obj     9: n_valid

__global__ void __launch_bounds__(128)
fused_kernel(const float* __restrict__ preds,
             const float* __restrict__ target,
             const float* __restrict__ anchors,
             const float* __restrict__ proto,
             const float* __restrict__ masks,
             float* __restrict__ out)
{
    const int c   = blockIdx.x;
    const int tid = threadIdx.x;

    const float* t = target + (size_t)c * 7;
    const float* p = preds  + (size_t)c * PC;

    __shared__ float tc[NM];
    __shared__ float sred[128];
    __shared__ float s_cls;
    __shared__ int   sh_y1, sh_ny, sh_x1, sh_nx, sh_area, sh_id;
    __shared__ int   sh_last;

    const float conf_t = t[4];
    const bool  obj    = (conf_t == 1.0f);

    if (!obj) {
        if (tid == 0) {
            const float nb = (conf_t == 0.0f) ? bce_logits(p[4], 0.0f) : 0.0f;
            g_part[0][c] = nb;
            g_part[1][c] = (conf_t == 0.0f) ? 1.0f : 0.0f;
            #pragma unroll
            for (int q = 2; q < NQ; q++) g_part[q][c] = 0.0f;
        }
    } else {
        // decode (n, a, i, j)
        const int n   = c / (A_ * S_ * S_);
        const int rem = c % (A_ * S_ * S_);
        const int a   = rem / (S_ * S_);
        const int ij  = rem % (S_ * S_);
        const int i   = ij / S_;
        const int j   = ij % S_;

        float v_obj = 0.f, v_giou1m = 0.f, v_xy = 0.f, v_wh = 0.f;

        // ---- warp 0 lane 0: box / giou / obj / xy / wh + region bounds ----
        if (tid == 0) {
            const float anw = anchors[a * 2 + 0];
            const float anh = anchors[a * 2 + 1];

            const float sx = 1.0f / (1.0f + expf(-p[0]));
            const float sy = 1.0f / (1.0f + expf(-p[1]));
            const float pw = expf(p[2]) * anw;
            const float ph = expf(p[3]) * anh;

            const float tx = t[0], ty = t[1], tw = t[2], th = t[3];

            const float eps = 1e-9f;
            const float b1x1 = sx - pw * 0.5f, b1y1 = sy - ph * 0.5f;
            const float b1x2 = sx + pw * 0.5f, b1y2 = sy + ph * 0.5f;
            const float b2x1 = tx - tw * 0.5f, b2y1 = ty - th * 0.5f;
            const float b2x2 = tx + tw * 0.5f, b2y2 = ty + th * 0.5f;
            const float a1 = fmaxf(b1x2 - b1x1, 0.0f) * fmaxf(b1y2 - b1y1, 0.0f) + eps;
            const float a2 = fmaxf(b2x2 - b2x1, 0.0f) * fmaxf(b2y2 - b2y1, 0.0f) + eps;
            const float iw = fmaxf(fminf(b1x2, b2x2) - fmaxf(b1x1, b2x1), 0.0f);
            const float ih = fmaxf(fminf(b1y2, b2y2) - fmaxf(b1y1, b2y1), 0.0f);
            const float inter = iw * ih + eps;
            const float uni   = a1 + a2 - inter + eps;
            const float iou   = inter / uni;
            const float cwd = fmaxf(b1x2, b2x2) - fminf(b1x1, b2x1);
            const float chd = fmaxf(b1y2, b2y2) - fminf(b1y1, b2y1);
            const float carea = cwd * chd + eps;
            const float giou  = iou - (carea - uni) / carea;

            v_giou1m = 1.0f - giou;
            v_obj    = bce_logits(p[4], conf_t * fmaxf(giou, 0.0f));
            v_xy     = bce_logits(sx, tx) + bce_logits(sy, ty);
            const float dw = p[2] - logf(1e-16f + tw / anw);
            const float dh = p[3] - logf(1e-16f + th / anh);
            v_wh     = dw * dw + dh * dh;

            // segment region bounds
            const float bx = (tx + (float)j) * ((float)W_ / (float)S_);
            const float by = (ty + (float)i) * ((float)H_ / (float)S_);
            const float bw = tw * ((float)W_ / (float)S_);
            const float bh = th * ((float)H_ / (float)S_);
            const int x1 = (int)floorf(bx - bw * 0.5f);
            const int x2 = (int)floorf(bx + bw * 0.5f);
            const int y1 = (int)floorf(by - bh * 0.5f);
            const int y2 = (int)floorf(by + bh * 0.5f);
            const int yl = max(y1, 0), yh = min(y2, H_);
            const int xl = max(x1, 0), xh = min(x2, W_);
            const int nrows = max(0, yh - yl);
            const int ncols = max(0, xh - xl);
            sh_y1 = yl; sh_ny = nrows;
            sh_x1 = xl; sh_nx = ncols;
            sh_area = nrows * ncols;
            int id = (int)t[6];
            sh_id = min(max(id, 0), G_ - 1);
        }

        // ---- warp 1: class log-softmax (shuffle-parallel over 80) ----
        if (tid >= 32 && tid < 64) {
            const int lane = tid - 32;
            float m = -3.4e38f;
            for (int k = lane; k < NC; k += 32) m = fmaxf(m, p[5 + k]);
            #pragma unroll
            for (int off = 16; off > 0; off >>= 1)
                m = fmaxf(m, __shfl_xor_sync(0xffffffffu, m, off));
            float se = 0.0f;
            for (int k = lane; k < NC; k += 32) se += expf(p[5 + k] - m);
            #pragma unroll
            for (int off = 16; off > 0; off >>= 1)
                se += __shfl_xor_sync(0xffffffffu, se, off);
            if (lane == 0) {
                const int lab = (int)t[5];
                s_cls = -(p[5 + lab] - m - logf(se));
            }
        }

        // ---- warp 2: tanh of the 32 mask coefficients ----
        if (tid >= 64 && tid < 96) tc[tid - 64] = tanhf(p[5 + NC + (tid - 64)]);

        __syncthreads();

        // ---- segment region sweep (all 128 threads) ----
        const int area = sh_area;
        float acc = 0.0f;
        if (area > 0) {
            const float* __restrict__ pr = proto + (size_t)n * NM * HW;
            const float* __restrict__ tm = masks + ((size_t)n * G_ + sh_id) * HW;
            const int npix = sh_ny * sh_nx;
            const int nx   = sh_nx;
            for (int pix = tid; pix < npix; pix += 128) {
                const int r  = pix / nx;
                const int cc = pix - r * nx;
                const int off = (sh_y1 + r) * W_ + (sh_x1 + cc);
                float dot = 0.0f;
                #pragma unroll
                for (int m = 0; m < NM; m++)
                    dot = fmaf(tc[m], pr[m * HW + off], dot);
                acc += bce_logits(dot, tm[off]);
            }
        }
        sred[tid] = acc;
        __syncthreads();
        #pragma unroll
        for (int s = 64; s > 0; s >>= 1) {
            if (tid < s) sred[tid] += sred[tid + s];
            __syncthreads();
        }

        if (tid == 0) {
            g_part[0][c] = 0.0f;
            g_part[1][c] = 0.0f;
            g_part[2][c] = v_obj;
            g_part[3][c] = v_giou1m;
            g_part[4][c] = v_xy;
            g_part[5][c] = v_wh;
            g_part[6][c] = s_cls;
            g_part[7][c] = (area > 0) ? sred[0] / (float)area : 0.0f;
            g_part[8][c] = 1.0f;
            g_part[9][c] = (area > 0) ? 1.0f : 0.0f;
        }
    }

    // ---- last-block reduction ----
    __threadfence();
    if (tid == 0) {
        const unsigned prev = atomicAdd(&g_count, 1u);
        sh_last = (prev == (unsigned)(gridDim.x - 1)) ? 1 : 0;
    }
    __syncthreads();
    if (!sh_last) return;

    __shared__ double dred[128];
    double fin[NQ];
    #pragma unroll
    for (int q = 0; q < NQ; q++) {
        double a = 0.0;
        for (int cc = tid; cc < NCELL; cc += 128) a += (double)g_part[q][cc];
        dred[tid] = a;
        __syncthreads();
        #pragma unroll
        for (int s = 64; s > 0; s >>= 1) {
            if (tid < s) dred[tid] += dred[tid + s];
            __syncthreads();
        }
        fin[q] = dred[0];
        __syncthreads();
    }

    if (tid == 0) {
        const double n_noobj = fin[1], n_obj = fin[8], n_valid = fin[9];
        const double noobj_loss = fin[0] / n_noobj;
        const double obj_loss   = fin[2] / n_obj;
        const double box_loss   = fin[4] / (n_obj * 2.0)
                                + fin[5] / (n_obj * 2.0)
                                + fin[3] / n_obj;
        const double class_loss = fin[6] / n_obj;
        const double seg_loss   = fin[7] / (n_valid + 1e-9);

        const double box_l   = 8.0  * box_loss;
        const double obj_l   = 2.0  * obj_loss;
        const double noobj_l = 4.0  * noobj_loss;
        const double cls_l   = 1.0  * class_loss;
        const double seg_l   = 10.0 * seg_loss;

        out[0] = (float)box_l;
        out[1] = (float)obj_l;
        out[2] = (float)noobj_l;
        out[3] = (float)cls_l;
        out[4] = (float)seg_l;
        out[5] = (float)(box_l + obj_l + noobj_l + cls_l + seg_l);

        g_count = 0;   // reset for next graph replay
    }
}

extern "C" void kernel_launch(void* const* d_in, const int* in_sizes, int n_in,
                              void* d_out, int out_size)
{
    const float* preds   = (const float*)d_in[0];
    const float* target  = (const float*)d_in[1];
    const float* anchors = (const float*)d_in[2];
    const float* proto   = (const float*)d_in[3];
    const float* masks   = (const float*)d_in[4];
    float* out = (float*)d_out;

    fused_kernel<<<NCELL, 128>>>(preds, target, anchors, proto, masks, out);
}